// round 6
// baseline (speedup 1.0000x reference)
#include <cuda_runtime.h>
#include <cstdint>

// ---------------- problem constants ----------------
#define NN 100000
#define VV 3
#define EE 500000
#define EPSL 1e-5f

#define BN 64          // nodes per tile
#define NT 256         // 8 warps; half-warp owns 4 rows
#define NTILES ((NN + BN - 1) / BN)   // 1563
#define FSP 132        // Fs row pitch (floats) — avoids bank conflict on dual broadcast

typedef unsigned long long ull;

// ---------------- scratch ----------------
__device__ float g_pre[(size_t)VV * NN * 128];
__device__ float g_wsum[VV * NN];
__device__ float g_selfout[(size_t)NN * 128];
__device__ float g_transformed[(size_t)NN * 128];
__device__ float g_nodeatt[NN];
__device__ float g_viewout[(size_t)VV * NN * 128];
__device__ float g_vscore[VV * NN];

// ---------------- helpers ----------------
__device__ __forceinline__ void ffma2(ull &d, ull a, ull b) {
    asm("fma.rn.f32x2 %0, %1, %2, %0;" : "+l"(d) : "l"(a), "l"(b));
}
__device__ __forceinline__ ull fdup(float a) {
    ull r; asm("mov.b64 %0, {%1, %1};" : "=l"(r) : "f"(a)); return r;
}
__device__ __forceinline__ float2 u2f(ull v) {
    float2 r; asm("mov.b64 {%0, %1}, %2;" : "=f"(r.x), "=f"(r.y) : "l"(v)); return r;
}
__device__ __forceinline__ float sigm(float x) { return 1.f / (1.f + __expf(-x)); }

// xor-reduce over 16-lane halves (offsets < 16 keep halves separate)
__device__ __forceinline__ float wred16(float x) {
#pragma unroll
    for (int off = 8; off > 0; off >>= 1)
        x += __shfl_xor_sync(0xffffffffu, x, off);
    return x;
}
// xor-reduce over 8-lane groups
__device__ __forceinline__ float wred8(float x) {
#pragma unroll
    for (int off = 4; off > 0; off >>= 1)
        x += __shfl_xor_sync(0xffffffffu, x, off);
    return x;
}

// ---------------- zero scratch ----------------
__global__ void k_zero() {
    size_t tid = (size_t)blockIdx.x * blockDim.x + threadIdx.x;
    size_t stride = (size_t)gridDim.x * blockDim.x;
    size_t total4 = ((size_t)VV * NN * 128) / 4;
    float4 z = make_float4(0.f, 0.f, 0.f, 0.f);
    for (size_t i = tid; i < total4; i += stride)
        reinterpret_cast<float4*>(g_pre)[i] = z;
    for (size_t i = tid; i < (size_t)VV * NN; i += stride)
        g_wsum[i] = 0.f;
}

// ---------------- edge scatter ----------------
__global__ void __launch_bounds__(256) k_edge(const int* __restrict__ src,
                                              const int* __restrict__ dst,
                                              const float* __restrict__ w,
                                              const float* __restrict__ feats) {
    int gw = (int)(((size_t)blockIdx.x * 256 + threadIdx.x) >> 5);
    if (gw >= VV * EE) return;
    int l = threadIdx.x & 31;
    int v = gw / EE;
    int s = src[gw];
    int d = dst[gw];
    float we = w[gw];
    float4 x = reinterpret_cast<const float4*>(feats + (size_t)s * 128)[l];
    float* p = g_pre + ((size_t)v * NN + d) * 128 + l * 4;
    asm volatile("red.global.add.v4.f32 [%0], {%1,%2,%3,%4};" ::
                 "l"(p), "f"(we * x.x), "f"(we * x.y), "f"(we * x.z), "f"(we * x.w)
                 : "memory");
    if (l == 0) atomicAdd(&g_wsum[v * NN + d], we);
}

// ---------------- half-warp-private row loader ----------------
// each lane loads its 8 columns for the half's 4 rows
__device__ __forceinline__ void load_rows(const float* __restrict__ g, int nb, int n0,
                                          int sub, float* __restrict__ Fs) {
#pragma unroll
    for (int i = 0; i < 4; ++i) {
        int n = nb + n0 + i;
        float4 v0 = make_float4(0.f, 0.f, 0.f, 0.f), v1 = v0;
        if (n < NN) {
            const float4* gp = reinterpret_cast<const float4*>(g + (size_t)n * 128 + sub * 8);
            v0 = gp[0]; v1 = gp[1];
        }
        float* fr = Fs + (n0 + i) * FSP + sub * 8;
        *reinterpret_cast<float4*>(fr) = v0;
        *reinterpret_cast<float4*>(fr + 4) = v1;
    }
}

// ---------------- 4x8 matmul: A broadcast from smem, B streamed via LDG ----------------
// acc[i][j] = packed cols (c0+2j, c0+2j+1), rows n0..n0+3
template <int BSTRIDE>
__device__ __forceinline__ void mm4x8g(const float* __restrict__ Fs, int n0,
                                       const float* __restrict__ wb, ull acc[4][4]) {
#pragma unroll 2
    for (int kk = 0; kk < 128; kk += 2) {
        float2 a2[4];
#pragma unroll
        for (int i = 0; i < 4; ++i)
            a2[i] = *reinterpret_cast<const float2*>(Fs + (n0 + i) * FSP + kk);
#pragma unroll
        for (int q = 0; q < 2; ++q) {
            const float* wr = wb + (kk + q) * BSTRIDE;
            ulonglong2 b0 = __ldg(reinterpret_cast<const ulonglong2*>(wr));
            ulonglong2 b1 = __ldg(reinterpret_cast<const ulonglong2*>(wr + 4));
#pragma unroll
            for (int i = 0; i < 4; ++i) {
                ull ad = fdup(q ? a2[i].y : a2[i].x);
                ffma2(acc[i][0], ad, b0.x);
                ffma2(acc[i][1], ad, b0.y);
                ffma2(acc[i][2], ad, b1.x);
                ffma2(acc[i][3], ad, b1.y);
            }
        }
    }
}

// 4x4 variant (OC=64)
__device__ __forceinline__ void mm4x4g(const float* __restrict__ Fs, int n0,
                                       const float* __restrict__ wb, ull acc[4][2]) {
#pragma unroll 2
    for (int kk = 0; kk < 128; kk += 2) {
        float2 a2[4];
#pragma unroll
        for (int i = 0; i < 4; ++i)
            a2[i] = *reinterpret_cast<const float2*>(Fs + (n0 + i) * FSP + kk);
#pragma unroll
        for (int q = 0; q < 2; ++q) {
            ulonglong2 b0 = __ldg(reinterpret_cast<const ulonglong2*>(wb + (kk + q) * 64));
#pragma unroll
            for (int i = 0; i < 4; ++i) {
                ull ad = fdup(q ? a2[i].y : a2[i].x);
                ffma2(acc[i][0], ad, b0.x);
                ffma2(acc[i][1], ad, b0.y);
            }
        }
    }
}

#define ZERO4x4(acc) do { _Pragma("unroll") for (int i = 0; i < 4; ++i) \
    _Pragma("unroll") for (int j = 0; j < 4; ++j) acc[i][j] = 0ull; } while (0)

// ---------------- feature-side kernel (no block syncs) ----------------
__global__ void __launch_bounds__(NT, 3) k_feat(
    const float* __restrict__ feats,
    const float* __restrict__ clsW, const float* __restrict__ clsb,
    const float* __restrict__ attW1, const float* __restrict__ attb1,
    const float* __restrict__ attW2, const float* __restrict__ attb2,
    const float* __restrict__ attbias,
    const float* __restrict__ selfW, const float* __restrict__ selfb,
    const float* __restrict__ featW, const float* __restrict__ featb,
    float* __restrict__ out_cp) {
    extern __shared__ float Fs[];   // BN*FSP

    int nb = blockIdx.x * BN;
    int t = threadIdx.x;
    int w = t >> 5, lane = t & 31;
    int half = (lane >> 4) & 1, sub = lane & 15;
    int n0 = (w * 2 + half) * 4;
    int c0 = sub * 8;

    load_rows(feats, nb, n0, sub, Fs);
    __syncwarp();

    ull acc[4][4];

    // ---- self_out ----
    ZERO4x4(acc);
    mm4x8g<128>(Fs, n0, selfW + c0, acc);
    {
        float4 b0 = __ldg(reinterpret_cast<const float4*>(selfb + c0));
        float4 b1 = __ldg(reinterpret_cast<const float4*>(selfb + c0) + 1);
#pragma unroll
        for (int i = 0; i < 4; ++i) {
            int n = nb + n0 + i;
            if (n < NN) {
                float2 p0 = u2f(acc[i][0]), p1 = u2f(acc[i][1]);
                float2 p2 = u2f(acc[i][2]), p3 = u2f(acc[i][3]);
                float4* o = reinterpret_cast<float4*>(g_selfout + (size_t)n * 128 + c0);
                o[0] = make_float4(p0.x + b0.x, p0.y + b0.y, p1.x + b0.z, p1.y + b0.w);
                o[1] = make_float4(p2.x + b1.x, p2.y + b1.y, p3.x + b1.z, p3.y + b1.w);
            }
        }
    }

    // ---- transformed ----
    ZERO4x4(acc);
    mm4x8g<128>(Fs, n0, featW + c0, acc);
    {
        float4 b0 = __ldg(reinterpret_cast<const float4*>(featb + c0));
        float4 b1 = __ldg(reinterpret_cast<const float4*>(featb + c0) + 1);
#pragma unroll
        for (int i = 0; i < 4; ++i) {
            int n = nb + n0 + i;
            if (n < NN) {
                float2 p0 = u2f(acc[i][0]), p1 = u2f(acc[i][1]);
                float2 p2 = u2f(acc[i][2]), p3 = u2f(acc[i][3]);
                float4* o = reinterpret_cast<float4*>(g_transformed + (size_t)n * 128 + c0);
                o[0] = make_float4(p0.x + b0.x, p0.y + b0.y, p1.x + b0.z, p1.y + b0.w);
                o[1] = make_float4(p2.x + b1.x, p2.y + b1.y, p3.x + b1.z, p3.y + b1.w);
            }
        }
    }

    // ---- label attention: cols c0 all in class cls ----
    float sc[4], sco[4];
    {
        int cls = c0 >> 6;
        ZERO4x4(acc);
        mm4x8g<64>(Fs, n0, attW1 + cls * 8192 + (c0 & 63), acc);
        float4 ab0 = __ldg(reinterpret_cast<const float4*>(attb1 + c0));
        float4 ab1 = __ldg(reinterpret_cast<const float4*>(attb1 + c0) + 1);
        float4 aw0 = __ldg(reinterpret_cast<const float4*>(attW2 + c0));
        float4 aw1 = __ldg(reinterpret_cast<const float4*>(attW2 + c0) + 1);
        float b2v = __ldg(attb2 + cls);
#pragma unroll
        for (int i = 0; i < 4; ++i) {
            float2 f0 = u2f(acc[i][0]), f1 = u2f(acc[i][1]);
            float2 f2 = u2f(acc[i][2]), f3 = u2f(acc[i][3]);
            float p = fmaxf(f0.x + ab0.x, 0.f) * aw0.x
                    + fmaxf(f0.y + ab0.y, 0.f) * aw0.y
                    + fmaxf(f1.x + ab0.z, 0.f) * aw0.z
                    + fmaxf(f1.y + ab0.w, 0.f) * aw0.w
                    + fmaxf(f2.x + ab1.x, 0.f) * aw1.x
                    + fmaxf(f2.y + ab1.y, 0.f) * aw1.y
                    + fmaxf(f3.x + ab1.z, 0.f) * aw1.z
                    + fmaxf(f3.y + ab1.w, 0.f) * aw1.w;
            p = wred8(p);                 // sum over the 8 lanes of this class
            sc[i] = sigm(p + b2v);        // valid on sub==0 (class0) / sub==8 (class1)
            sco[i] = __shfl_xor_sync(0xffffffffu, sc[i], 8);   // the other class
        }
    }

    // ---- class probs + node_att (per-lane partials over own 8 cols) ----
    {
        float4 cw0 = __ldg(reinterpret_cast<const float4*>(clsW + c0 * 2));
        float4 cw1 = __ldg(reinterpret_cast<const float4*>(clsW + c0 * 2) + 1);
        float4 cw2 = __ldg(reinterpret_cast<const float4*>(clsW + c0 * 2) + 2);
        float4 cw3 = __ldg(reinterpret_cast<const float4*>(clsW + c0 * 2) + 3);
        float cb0 = __ldg(clsb), cb1 = __ldg(clsb + 1), abv = __ldg(attbias);
#pragma unroll
        for (int i = 0; i < 4; ++i) {
            const float* fr = Fs + (n0 + i) * FSP + c0;
            float4 f0 = *reinterpret_cast<const float4*>(fr);
            float4 f1 = *reinterpret_cast<const float4*>(fr + 4);
            float p0 = f0.x * cw0.x + f0.y * cw0.z + f0.z * cw1.x + f0.w * cw1.z
                     + f1.x * cw2.x + f1.y * cw2.z + f1.z * cw3.x + f1.w * cw3.z;
            float p1 = f0.x * cw0.y + f0.y * cw0.w + f0.z * cw1.y + f0.w * cw1.w
                     + f1.x * cw2.y + f1.y * cw2.w + f1.z * cw3.y + f1.w * cw3.w;
            p0 = wred16(p0);
            p1 = wred16(p1);
            int n = nb + n0 + i;
            if (sub == 0 && n < NN) {
                float l0 = p0 + cb0, l1 = p1 + cb1;
                float m = fmaxf(l0, l1);
                float e0 = __expf(l0 - m), e1 = __expf(l1 - m);
                float inv = 1.f / (e0 + e1);
                float cp0 = e0 * inv, cp1 = e1 * inv;
                out_cp[(size_t)n * 2] = cp0;
                out_cp[(size_t)n * 2 + 1] = cp1;
                // half 0 lane0: sc=class0, sco=class1; half 1 lane16: same (sub==0)
                g_nodeatt[n] = sc[i] * cp0 + sco[i] * cp1 + abv;
            }
        }
    }
}

// ---------------- per-view kernel (no block syncs) ----------------
__global__ void __launch_bounds__(NT, 3) k_view(
    const float* __restrict__ relW, const float* __restrict__ relb,
    const float* __restrict__ gateW, const float* __restrict__ gateb,
    const float* __restrict__ view_pref,
    const float* __restrict__ vattW1, const float* __restrict__ vattb1,
    const float* __restrict__ vattW2, const float* __restrict__ vattb2) {
    extern __shared__ float Fs[];

    int v = blockIdx.y;
    int nb = blockIdx.x * BN;
    int t = threadIdx.x;
    int w = t >> 5, lane = t & 31;
    int half = (lane >> 4) & 1, sub = lane & 15;
    int n0 = (w * 2 + half) * 4;
    int c0 = sub * 8;

    load_rows(g_pre + (size_t)v * NN * 128, nb, n0, sub, Fs);
    __syncwarp();

    // ---- agg = pre @ relW + wsum * relb ----
    ull acc[4][4];
    ZERO4x4(acc);
    mm4x8g<128>(Fs, n0, relW + (size_t)v * 16384 + c0, acc);
    {
        ulonglong2 r01 = __ldg(reinterpret_cast<const ulonglong2*>(relb + v * 128 + c0));
        ulonglong2 r23 = __ldg(reinterpret_cast<const ulonglong2*>(relb + v * 128 + c0) + 1);
#pragma unroll
        for (int i = 0; i < 4; ++i) {
            int n = nb + n0 + i;
            float ws = (n < NN) ? __ldg(g_wsum + v * NN + n) : 0.f;
            ull wd = fdup(ws);
            ffma2(acc[i][0], wd, r01.x);
            ffma2(acc[i][1], wd, r01.y);
            ffma2(acc[i][2], wd, r23.x);
            ffma2(acc[i][3], wd, r23.y);
        }
    }
    // stash agg into own cols of own rows
#pragma unroll
    for (int i = 0; i < 4; ++i) {
        float2 p0 = u2f(acc[i][0]), p1 = u2f(acc[i][1]);
        float2 p2 = u2f(acc[i][2]), p3 = u2f(acc[i][3]);
        float* fr = Fs + (n0 + i) * FSP + c0;
        *reinterpret_cast<float4*>(fr) = make_float4(p0.x, p0.y, p1.x, p1.y);
        *reinterpret_cast<float4*>(fr + 4) = make_float4(p2.x, p2.y, p3.x, p3.y);
    }
    __syncwarp();

    // ---- gate GEMM ----
    ull gac[4][4];
    ZERO4x4(gac);
    mm4x8g<128>(Fs, n0, gateW + (size_t)v * 16384 + c0, gac);

    // ---- view_out = sigm(gate+gb) * agg; store + stash vo*vpref ----
    {
        float4 gb0 = __ldg(reinterpret_cast<const float4*>(gateb + v * 128 + c0));
        float4 gb1 = __ldg(reinterpret_cast<const float4*>(gateb + v * 128 + c0) + 1);
        float4 vp0 = __ldg(reinterpret_cast<const float4*>(view_pref + v * 128 + c0));
        float4 vp1 = __ldg(reinterpret_cast<const float4*>(view_pref + v * 128 + c0) + 1);
#pragma unroll
        for (int i = 0; i < 4; ++i) {
            int n = nb + n0 + i;
            float* fr = Fs + (n0 + i) * FSP + c0;
            float4 a0 = *reinterpret_cast<const float4*>(fr);
            float4 a1 = *reinterpret_cast<const float4*>(fr + 4);
            float2 g0 = u2f(gac[i][0]), g1 = u2f(gac[i][1]);
            float2 g2 = u2f(gac[i][2]), g3 = u2f(gac[i][3]);
            float vo0 = sigm(g0.x + gb0.x) * a0.x;
            float vo1 = sigm(g0.y + gb0.y) * a0.y;
            float vo2 = sigm(g1.x + gb0.z) * a0.z;
            float vo3 = sigm(g1.y + gb0.w) * a0.w;
            float vo4 = sigm(g2.x + gb1.x) * a1.x;
            float vo5 = sigm(g2.y + gb1.y) * a1.y;
            float vo6 = sigm(g3.x + gb1.z) * a1.z;
            float vo7 = sigm(g3.y + gb1.w) * a1.w;
            if (n < NN) {
                float4* o = reinterpret_cast<float4*>(g_viewout + ((size_t)v * NN + n) * 128 + c0);
                o[0] = make_float4(vo0, vo1, vo2, vo3);
                o[1] = make_float4(vo4, vo5, vo6, vo7);
            }
            *reinterpret_cast<float4*>(fr) = make_float4(vo0 * vp0.x, vo1 * vp0.y, vo2 * vp0.z, vo3 * vp0.w);
            *reinterpret_cast<float4*>(fr + 4) = make_float4(vo4 * vp1.x, vo5 * vp1.y, vo6 * vp1.z, vo7 * vp1.w);
        }
    }
    __syncwarp();

    // ---- view-attention score ----
    {
        int cv = sub * 4;
        ull vac[4][2];
#pragma unroll
        for (int i = 0; i < 4; ++i) { vac[i][0] = 0ull; vac[i][1] = 0ull; }
        mm4x4g(Fs, n0, vattW1 + cv, vac);
        float4 vb = __ldg(reinterpret_cast<const float4*>(vattb1 + cv));
        float4 vw = __ldg(reinterpret_cast<const float4*>(vattW2 + cv));
        float b2v = __ldg(vattb2);
#pragma unroll
        for (int i = 0; i < 4; ++i) {
            float2 f0 = u2f(vac[i][0]), f1 = u2f(vac[i][1]);
            float s = fmaxf(f0.x + vb.x, 0.f) * vw.x
                    + fmaxf(f0.y + vb.y, 0.f) * vw.y
                    + fmaxf(f1.x + vb.z, 0.f) * vw.z
                    + fmaxf(f1.y + vb.w, 0.f) * vw.w;
            s = wred16(s);
            int n = nb + n0 + i;
            if (sub == 0 && n < NN) g_vscore[v * NN + n] = s + b2v;
        }
    }
}

// ---------------- fusion + residual + layer norm (no block syncs) ----------------
__global__ void __launch_bounds__(NT, 3) k_fuse(
    const float* __restrict__ fusW, const float* __restrict__ fusb,
    const float* __restrict__ ln_g, const float* __restrict__ ln_b,
    float* __restrict__ out) {
    extern __shared__ float Zs[];

    int nb = blockIdx.x * BN;
    int t = threadIdx.x;
    int w = t >> 5, lane = t & 31;
    int half = (lane >> 4) & 1, sub = lane & 15;
    int n0 = (w * 2 + half) * 4;
    int c0 = sub * 8;

    // per-row softmax-over-views weight * node_att (redundant per lane)
    float vw0[4], vw1[4], vw2[4];
#pragma unroll
    for (int i = 0; i < 4; ++i) {
        int n = nb + n0 + i;
        float s0 = 0.f, s1 = 0.f, s2 = 0.f, na = 0.f;
        if (n < NN) {
            s0 = __ldg(g_vscore + n);
            s1 = __ldg(g_vscore + NN + n);
            s2 = __ldg(g_vscore + 2 * NN + n);
            na = __ldg(g_nodeatt + n);
        }
        float m = fmaxf(s0, fmaxf(s1, s2));
        float e0 = __expf(s0 - m), e1 = __expf(s1 - m), e2 = __expf(s2 - m);
        float inv = na / (e0 + e1 + e2);
        vw0[i] = e0 * inv; vw1[i] = e1 * inv; vw2[i] = e2 * inv;
    }

    load_rows(g_selfout, nb, n0, sub, Zs);
    __syncwarp();

    // phase A: self_out @ fusW rows [0,128)
    ull acc[4][4];
    ZERO4x4(acc);
    mm4x8g<128>(Zs, n0, fusW + c0, acc);

    // phase B: rebuild own rows = weighted view combo
#pragma unroll
    for (int i = 0; i < 4; ++i) {
        int n = nb + n0 + i;
        float4 a0 = make_float4(0.f, 0.f, 0.f, 0.f), a1 = a0;
        if (n < NN) {
            const float4* x0 = reinterpret_cast<const float4*>(g_viewout + (size_t)n * 128 + c0);
            const float4* x1 = reinterpret_cast<const float4*>(g_viewout + ((size_t)NN + n) * 128 + c0);
            const float4* x2 = reinterpret_cast<const float4*>(g_viewout + ((size_t)2 * NN + n) * 128 + c0);
            float4 p0 = x0[0], p1 = x1[0], p2 = x2[0];
            float4 q0 = x0[1], q1 = x1[1], q2 = x2[1];
            a0.x = vw0[i] * p0.x + vw1[i] * p1.x + vw2[i] * p2.x;
            a0.y = vw0[i] * p0.y + vw1[i] * p1.y + vw2[i] * p2.y;
            a0.z = vw0[i] * p0.z + vw1[i] * p1.z + vw2[i] * p2.z;
            a0.w = vw0[i] * p0.w + vw1[i] * p1.w + vw2[i] * p2.w;
            a1.x = vw0[i] * q0.x + vw1[i] * q1.x + vw2[i] * q2.x;
            a1.y = vw0[i] * q0.y + vw1[i] * q1.y + vw2[i] * q2.y;
            a1.z = vw0[i] * q0.z + vw1[i] * q1.z + vw2[i] * q2.z;
            a1.w = vw0[i] * q0.w + vw1[i] * q1.w + vw2[i] * q2.w;
        }
        float* zr = Zs + (n0 + i) * FSP + c0;
        *reinterpret_cast<float4*>(zr) = a0;
        *reinterpret_cast<float4*>(zr + 4) = a1;
    }
    __syncwarp();
    mm4x8g<128>(Zs, n0, fusW + 16384 + c0, acc);

    // epilogue: relu(+fusb) + transformed; LN via 16-lane reduce
    {
        float4 fb0 = __ldg(reinterpret_cast<const float4*>(fusb + c0));
        float4 fb1 = __ldg(reinterpret_cast<const float4*>(fusb + c0) + 1);
        float4 lg0 = __ldg(reinterpret_cast<const float4*>(ln_g + c0));
        float4 lg1 = __ldg(reinterpret_cast<const float4*>(ln_g + c0) + 1);
        float4 lb0 = __ldg(reinterpret_cast<const float4*>(ln_b + c0));
        float4 lb1 = __ldg(reinterpret_cast<const float4*>(ln_b + c0) + 1);
#pragma unroll
        for (int i = 0; i < 4; ++i) {
            int n = nb + n0 + i;
            float4 t0 = make_float4(0.f, 0.f, 0.f, 0.f), t1 = t0;
            if (n < NN) {
                const float4* tp = reinterpret_cast<const float4*>(g_transformed + (size_t)n * 128 + c0);
                t0 = tp[0]; t1 = tp[1];
            }
            float2 l0 = u2f(acc[i][0]), l1 = u2f(acc[i][1]);
            float2 l2 = u2f(acc[i][2]), l3 = u2f(acc[i][3]);
            float f[8];
            f[0] = fmaxf(l0.x + fb0.x, 0.f) + t0.x;
            f[1] = fmaxf(l0.y + fb0.y, 0.f) + t0.y;
            f[2] = fmaxf(l1.x + fb0.z, 0.f) + t0.z;
            f[3] = fmaxf(l1.y + fb0.w, 0.f) + t0.w;
            f[4] = fmaxf(l2.x + fb1.x, 0.f) + t1.x;
            f[5] = fmaxf(l2.y + fb1.y, 0.f) + t1.y;
            f[6] = fmaxf(l3.x + fb1.z, 0.f) + t1.z;
            f[7] = fmaxf(l3.y + fb1.w, 0.f) + t1.w;
            float s = 0.f, s2 = 0.f;
#pragma unroll
            for (int j = 0; j < 8; ++j) { s += f[j]; s2 = fmaf(f[j], f[j], s2); }
            s = wred16(s);
            s2 = wred16(s2);
            if (n < NN) {
                float mu = s * (1.f / 128.f);
                float var = s2 * (1.f / 128.f) - mu * mu;
                float rs = rsqrtf(var + EPSL);
                float4* op = reinterpret_cast<float4*>(out + (size_t)n * 128 + c0);
                op[0] = make_float4((f[0] - mu) * rs * lg0.x + lb0.x,
                                    (f[1] - mu) * rs * lg0.y + lb0.y,
                                    (f[2] - mu) * rs * lg0.z + lb0.z,
                                    (f[3] - mu) * rs * lg0.w + lb0.w);
                op[1] = make_float4((f[4] - mu) * rs * lg1.x + lb1.x,
                                    (f[5] - mu) * rs * lg1.y + lb1.y,
                                    (f[6] - mu) * rs * lg1.z + lb1.z,
                                    (f[7] - mu) * rs * lg1.w + lb1.w);
            }
        }
    }
}

// ---------------- launch ----------------
extern "C" void kernel_launch(void* const* d_in, const int* in_sizes, int n_in,
                              void* d_out, int out_size) {
    const float* feats   = (const float*)d_in[0];
    const int*   esrc    = (const int*)d_in[1];
    const int*   edst    = (const int*)d_in[2];
    const float* ew      = (const float*)d_in[3];
    const float* clsW    = (const float*)d_in[4];
    const float* clsb    = (const float*)d_in[5];
    const float* attW1   = (const float*)d_in[6];
    const float* attb1   = (const float*)d_in[7];
    const float* attW2   = (const float*)d_in[8];
    const float* attb2   = (const float*)d_in[9];
    const float* attbias = (const float*)d_in[10];
    const float* relW    = (const float*)d_in[11];
    const float* relb    = (const float*)d_in[12];
    const float* gateW   = (const float*)d_in[13];
    const float* gateb   = (const float*)d_in[14];
    const float* vpref   = (const float*)d_in[15];
    const float* vattW1  = (const float*)d_in[16];
    const float* vattb1  = (const float*)d_in[17];
    const float* vattW2  = (const float*)d_in[18];
    const float* vattb2  = (const float*)d_in[19];
    const float* selfW   = (const float*)d_in[20];
    const float* selfb   = (const float*)d_in[21];
    const float* featW   = (const float*)d_in[22];
    const float* featb   = (const float*)d_in[23];
    const float* fusW    = (const float*)d_in[24];
    const float* fusb    = (const float*)d_in[25];
    const float* lng     = (const float*)d_in[26];
    const float* lnb     = (const float*)d_in[27];

    float* out = (float*)d_out;
    float* out_cp = out + (size_t)NN * 128;

    const int SMEM = BN * FSP * 4;   // 33792 bytes, under the 48KB default cap

    k_zero<<<2048, 256>>>();

    {
        long long warps = (long long)VV * EE;
        int blocks = (int)((warps * 32 + 255) / 256);
        k_edge<<<blocks, 256>>>(esrc, edst, ew, feats);
    }

    k_feat<<<NTILES, NT, SMEM>>>(feats, clsW, clsb, attW1, attb1, attW2, attb2,
                                 attbias, selfW, selfb, featW, featb, out_cp);

    dim3 gv(NTILES, VV);
    k_view<<<gv, NT, SMEM>>>(relW, relb, gateW, gateb, vpref,
                             vattW1, vattb1, vattW2, vattb2);

    k_fuse<<<NTILES, NT, SMEM>>>(fusW, fusb, lng, lnb, out);
}

// round 7
// speedup vs baseline: 1.5240x; 1.5240x over previous
#include <cuda_runtime.h>
#include <cstdint>

// ---------------- problem constants ----------------
#define NN 100000
#define VV 3
#define EE 500000
#define EPSL 1e-5f

#define BN 128         // nodes per tile
#define NT 512         // 16 warps; warp = 8-node row group
#define NTILES ((NN + BN - 1) / BN)   // 782

typedef unsigned long long ull;

// ---------------- scratch (device globals; no allocation) ----------------
__device__ float g_pre[(size_t)VV * NN * 128];
__device__ float g_wsum[VV * NN];
__device__ float g_transformed[(size_t)NN * 128];
__device__ float g_nodeatt[NN];
__device__ float g_viewout[(size_t)VV * NN * 128];
__device__ float g_vscore[VV * NN];
__device__ float g_W01[128 * 128];    // selfW @ fusW[0:128]
__device__ float g_b01[128];          // fusb + selfb @ fusW[0:128]

// ---------------- small helpers ----------------
__device__ __forceinline__ void ffma2(ull &d, ull a, ull b) {
    asm("fma.rn.f32x2 %0, %1, %2, %0;" : "+l"(d) : "l"(a), "l"(b));
}
__device__ __forceinline__ ull fdup(float a) {
    ull r; asm("mov.b64 %0, {%1, %1};" : "=l"(r) : "f"(a)); return r;
}
__device__ __forceinline__ float2 u2f(ull v) {
    float2 r; asm("mov.b64 {%0, %1}, %2;" : "=f"(r.x), "=f"(r.y) : "l"(v)); return r;
}
__device__ __forceinline__ float sigm(float x) { return 1.f / (1.f + __expf(-x)); }

__device__ __forceinline__ unsigned smaddr(const void* p) {
    unsigned r;
    asm("{ .reg .u64 t; cvta.to.shared.u64 t, %1; cvt.u32.u64 %0, t; }" : "=r"(r) : "l"(p));
    return r;
}
#define MBAR_INIT(a) asm volatile("mbarrier.init.shared.b64 [%0], 1;" :: "r"(a))
#define MBAR_EXPECT(a, bytes) \
    asm volatile("mbarrier.arrive.expect_tx.shared.b64 _, [%0], %1;" :: "r"(a), "r"(bytes))
#define MBAR_WAIT(a, parity) do { \
    unsigned _p = 0; \
    while (!_p) { \
        asm volatile("{\n\t.reg .pred P;\n\t" \
                     "mbarrier.try_wait.parity.shared.b64 P, [%1], %2, 0x989680;\n\t" \
                     "selp.u32 %0, 1, 0, P;\n\t}" \
                     : "=r"(_p) : "r"(a), "r"((unsigned)(parity))); \
    } } while (0)

__device__ __forceinline__ void bulk_g2s(unsigned dst, const void* src, unsigned bytes, unsigned mbar) {
    asm volatile("cp.async.bulk.shared::cluster.global.mbarrier::complete_tx::bytes [%0], [%1], %2, [%3];"
                 :: "r"(dst), "l"(src), "r"(bytes), "r"(mbar) : "memory");
}

__device__ __forceinline__ float wred32(float x) {
#pragma unroll
    for (int off = 16; off > 0; off >>= 1)
        x += __shfl_xor_sync(0xffffffffu, x, off);
    return x;
}
__device__ __forceinline__ float wred16(float x) {
#pragma unroll
    for (int off = 8; off > 0; off >>= 1)
        x += __shfl_xor_sync(0xffffffffu, x, off);
    return x;
}

// ---------------- zero scratch ----------------
__global__ void k_zero() {
    size_t tid = (size_t)blockIdx.x * blockDim.x + threadIdx.x;
    size_t stride = (size_t)gridDim.x * blockDim.x;
    size_t total4 = ((size_t)VV * NN * 128) / 4;
    float4 z = make_float4(0.f, 0.f, 0.f, 0.f);
    for (size_t i = tid; i < total4; i += stride)
        reinterpret_cast<float4*>(g_pre)[i] = z;
    for (size_t i = tid; i < (size_t)VV * NN; i += stride)
        g_wsum[i] = 0.f;
}

// ---------------- precompute W01 = selfW @ fusW[0:128), b01 = fusb + selfb @ fusW1 ----------------
__global__ void k_pre(const float* __restrict__ selfW, const float* __restrict__ selfb,
                      const float* __restrict__ fusW, const float* __restrict__ fusb) {
    int c = threadIdx.x;          // 0..127 output col
    int i = blockIdx.x;           // 0..127 input row
    float s = 0.f;
#pragma unroll 8
    for (int m = 0; m < 128; ++m)
        s = fmaf(selfW[i * 128 + m], __ldg(fusW + m * 128 + c), s);
    g_W01[i * 128 + c] = s;
    if (i == 0) {
        float b = __ldg(fusb + c);
#pragma unroll 8
        for (int m = 0; m < 128; ++m)
            b = fmaf(__ldg(selfb + m), __ldg(fusW + m * 128 + c), b);
        g_b01[c] = b;
    }
}

// ---------------- edge scatter ----------------
__global__ void __launch_bounds__(256) k_edge(const int* __restrict__ src,
                                              const int* __restrict__ dst,
                                              const float* __restrict__ w,
                                              const float* __restrict__ feats) {
    int gw = (int)(((size_t)blockIdx.x * 256 + threadIdx.x) >> 5);
    if (gw >= VV * EE) return;
    int l = threadIdx.x & 31;
    int v = gw / EE;
    int s = src[gw];
    int d = dst[gw];
    float we = w[gw];
    float4 x = reinterpret_cast<const float4*>(feats + (size_t)s * 128)[l];
    float* p = g_pre + ((size_t)v * NN + d) * 128 + l * 4;
    asm volatile("red.global.add.v4.f32 [%0], {%1,%2,%3,%4};" ::
                 "l"(p), "f"(we * x.x), "f"(we * x.y), "f"(we * x.z), "f"(we * x.w)
                 : "memory");
    if (l == 0) atomicAdd(&g_wsum[v * NN + d], we);
}

// ---------------- warp-private tile loader ----------------
__device__ __forceinline__ void load_rows_warp(const float* __restrict__ g, int nb, int n0,
                                               int lane, float* __restrict__ Fs) {
#pragma unroll
    for (int i = 0; i < 8; ++i) {
        int n = nb + n0 + i;
        float4 v = make_float4(0.f, 0.f, 0.f, 0.f);
        if (n < NN) v = reinterpret_cast<const float4*>(g + (size_t)n * 128)[lane];
        reinterpret_cast<float4*>(Fs + (n0 + i) * 128)[lane] = v;
    }
}

// ---------------- 8x4 register-blocked matmul, FFMA2, broadcast A ----------------
template <int BSTRIDE>
__device__ __forceinline__ void mm8x4(const float* __restrict__ Fs, const float* __restrict__ wbase,
                                      ull acc2[8][2], int n0) {
#pragma unroll 2
    for (int kk = 0; kk < 128; kk += 4) {
        float4 a4[8];
#pragma unroll
        for (int i = 0; i < 8; ++i)
            a4[i] = *reinterpret_cast<const float4*>(Fs + (n0 + i) * 128 + kk);
#pragma unroll
        for (int q = 0; q < 4; ++q) {
            ulonglong2 b = *reinterpret_cast<const ulonglong2*>(wbase + (kk + q) * BSTRIDE);
#pragma unroll
            for (int i = 0; i < 8; ++i) {
                float av = (q == 0) ? a4[i].x : (q == 1) ? a4[i].y : (q == 2) ? a4[i].z : a4[i].w;
                ull ad = fdup(av);
                ffma2(acc2[i][0], ad, b.x);
                ffma2(acc2[i][1], ad, b.y);
            }
        }
    }
}

__device__ __forceinline__ void mm8x2_64(const float* __restrict__ Fs, const float* __restrict__ wbase,
                                         ull acc[8], int n0) {
#pragma unroll 2
    for (int kk = 0; kk < 128; kk += 4) {
        float4 a4[8];
#pragma unroll
        for (int i = 0; i < 8; ++i)
            a4[i] = *reinterpret_cast<const float4*>(Fs + (n0 + i) * 128 + kk);
#pragma unroll
        for (int q = 0; q < 4; ++q) {
            ull b = *reinterpret_cast<const ull*>(wbase + (kk + q) * 64);
#pragma unroll
            for (int i = 0; i < 8; ++i) {
                float av = (q == 0) ? a4[i].x : (q == 1) ? a4[i].y : (q == 2) ? a4[i].z : a4[i].w;
                ffma2(acc[i], fdup(av), b);
            }
        }
    }
}

#define ZERO_ACC(acc2) do { \
    _Pragma("unroll") for (int i = 0; i < 8; ++i) { acc2[i][0] = 0ull; acc2[i][1] = 0ull; } } while (0)

// ---------------- feature-side kernel ----------------
// smem: [0:4) mbars | Fs 16384 | W0 16384 | W1 16384 | clsWs 256 | scoreS 256
__global__ void __launch_bounds__(NT, 1) k_feat(
    const float* __restrict__ feats,
    const float* __restrict__ clsW, const float* __restrict__ clsb,
    const float* __restrict__ attW1, const float* __restrict__ attb1,
    const float* __restrict__ attW2, const float* __restrict__ attb2,
    const float* __restrict__ attbias,
    const float* __restrict__ featW, const float* __restrict__ featb,
    float* __restrict__ out_cp) {
    extern __shared__ float sm[];
    float* Fs = sm + 4;
    float* W0 = Fs + 16384;
    float* W1 = W0 + 16384;
    float* clsWs = W1 + 16384;
    float* scoreS = clsWs + 256;
    unsigned mb0 = smaddr(sm), mb1 = mb0 + 8;

    int nb = blockIdx.x * BN;
    int t = threadIdx.x;
    int lane = t & 31;
    int ng = t >> 5;
    int n0 = ng * 8, c0 = lane * 4;

    if (t == 0) { MBAR_INIT(mb0); MBAR_INIT(mb1); }
    __syncthreads();
    if (t == 0) {
        MBAR_EXPECT(mb0, 65536u);
        bulk_g2s(smaddr(W0), featW, 65536u, mb0);
        MBAR_EXPECT(mb1, 65536u);
        bulk_g2s(smaddr(W1), attW1, 65536u, mb1);   // [2][128][64] = 16384 floats
    }
    load_rows_warp(feats, nb, n0, lane, Fs);
    if (t < 64)
        reinterpret_cast<float4*>(clsWs)[t] = __ldg(reinterpret_cast<const float4*>(clsW) + t);
    __syncwarp();

    ull acc2[8][2];

    // ---- transformed = f @ featW + featb ----
    MBAR_WAIT(mb0, 0);
    ZERO_ACC(acc2);
    mm8x4<128>(Fs, W0 + c0, acc2, n0);
    {
        float4 b0 = __ldg(reinterpret_cast<const float4*>(featb + c0));
#pragma unroll
        for (int i = 0; i < 8; ++i) {
            int n = nb + n0 + i;
            if (n < NN) {
                float2 p0 = u2f(acc2[i][0]), p1 = u2f(acc2[i][1]);
                *reinterpret_cast<float4*>(g_transformed + (size_t)n * 128 + c0) =
                    make_float4(p0.x + b0.x, p0.y + b0.y, p1.x + b0.z, p1.y + b0.w);
            }
        }
    }

    // ---- label attention: h = relu(f @ attW1 + b1), score = sigm(h . attW2 + b2) ----
    MBAR_WAIT(mb1, 0);
    ZERO_ACC(acc2);
    {
        int cls = c0 >> 6;
        mm8x4<64>(Fs, W1 + cls * 8192 + (c0 & 63), acc2, n0);
        float4 ab = __ldg(reinterpret_cast<const float4*>(attb1 + c0));
        float4 aw = __ldg(reinterpret_cast<const float4*>(attW2 + c0));
        float b2v = __ldg(attb2 + cls);
#pragma unroll
        for (int i = 0; i < 8; ++i) {
            float2 f0 = u2f(acc2[i][0]), f1 = u2f(acc2[i][1]);
            float p = fmaxf(f0.x + ab.x, 0.f) * aw.x
                    + fmaxf(f0.y + ab.y, 0.f) * aw.y
                    + fmaxf(f1.x + ab.z, 0.f) * aw.z
                    + fmaxf(f1.y + ab.w, 0.f) * aw.w;
            p = wred16(p);
            if ((lane & 15) == 0)
                scoreS[cls * 128 + n0 + i] = sigm(p + b2v);
        }
    }
    __syncthreads();

    // ---- class probs + node_att (threads 0..127, node = t) ----
    if (t < 128) {
        int nl = t, n = nb + nl;
        if (n < NN) {
            float l0 = __ldg(clsb), l1 = __ldg(clsb + 1);
#pragma unroll 8
            for (int q = 0; q < 32; ++q) {
                int kq = (q + nl) & 31;
                float4 f = reinterpret_cast<const float4*>(Fs + nl * 128)[kq];
                const float* cw = clsWs + kq * 8;
                l0 = fmaf(f.x, cw[0], l0); l1 = fmaf(f.x, cw[1], l1);
                l0 = fmaf(f.y, cw[2], l0); l1 = fmaf(f.y, cw[3], l1);
                l0 = fmaf(f.z, cw[4], l0); l1 = fmaf(f.z, cw[5], l1);
                l0 = fmaf(f.w, cw[6], l0); l1 = fmaf(f.w, cw[7], l1);
            }
            float m = fmaxf(l0, l1);
            float e0 = __expf(l0 - m), e1 = __expf(l1 - m);
            float inv = 1.f / (e0 + e1);
            float cp0 = e0 * inv, cp1 = e1 * inv;
            out_cp[(size_t)n * 2] = cp0;
            out_cp[(size_t)n * 2 + 1] = cp1;
            g_nodeatt[n] = scoreS[nl] * cp0 + scoreS[128 + nl] * cp1 + __ldg(attbias);
        }
    }
}

// ---------------- per-view kernel ----------------
// smem: [0:4) mbars | Fs 16384 | W0 16384 | W1 16384 | wsumS 128
__global__ void __launch_bounds__(NT, 1) k_view(
    const float* __restrict__ relW, const float* __restrict__ relb,
    const float* __restrict__ gateW, const float* __restrict__ gateb,
    const float* __restrict__ view_pref,
    const float* __restrict__ vattW1, const float* __restrict__ vattb1,
    const float* __restrict__ vattW2, const float* __restrict__ vattb2) {
    extern __shared__ float sm[];
    float* Fs = sm + 4;
    float* W0 = Fs + 16384;
    float* W1 = W0 + 16384;
    float* wsumS = W1 + 16384;
    unsigned mb0 = smaddr(sm), mb1 = mb0 + 8;

    int v = blockIdx.y;
    int nb = blockIdx.x * BN;
    int t = threadIdx.x;
    int lane = t & 31;
    int ng = t >> 5;
    int n0 = ng * 8, c0 = lane * 4;

    if (t == 0) { MBAR_INIT(mb0); MBAR_INIT(mb1); }
    __syncthreads();
    if (t == 0) {
        MBAR_EXPECT(mb0, 65536u);
        bulk_g2s(smaddr(W0), relW + (size_t)v * 16384, 65536u, mb0);
        MBAR_EXPECT(mb1, 65536u);
        bulk_g2s(smaddr(W1), gateW + (size_t)v * 16384, 65536u, mb1);
    }
    load_rows_warp(g_pre + (size_t)v * NN * 128, nb, n0, lane, Fs);
    if (t < 128) {
        int n = nb + t;
        wsumS[t] = (n < NN) ? g_wsum[v * NN + n] : 0.f;
    }
    __syncthreads();

    // ---- agg = pre @ relW + wsum * relb ----
    ull acc2[8][2];
    MBAR_WAIT(mb0, 0);
    ZERO_ACC(acc2);
    mm8x4<128>(Fs, W0 + c0, acc2, n0);
    {
        ulonglong2 r01 = __ldg(reinterpret_cast<const ulonglong2*>(relb + v * 128 + c0));
#pragma unroll
        for (int i = 0; i < 8; ++i) {
            ull wd = fdup(wsumS[n0 + i]);
            ffma2(acc2[i][0], wd, r01.x);
            ffma2(acc2[i][1], wd, r01.y);
        }
    }
#pragma unroll
    for (int i = 0; i < 8; ++i) {
        float2 p0 = u2f(acc2[i][0]), p1 = u2f(acc2[i][1]);
        *reinterpret_cast<float4*>(Fs + (n0 + i) * 128 + c0) = make_float4(p0.x, p0.y, p1.x, p1.y);
    }
    __syncthreads();
    if (t == 0) {
        MBAR_EXPECT(mb0, 32768u);
        bulk_g2s(smaddr(W0), vattW1, 32768u, mb0);
    }

    // ---- gate matmul on agg ----
    ull gac2[8][2];
    MBAR_WAIT(mb1, 0);
#pragma unroll
    for (int i = 0; i < 8; ++i) { gac2[i][0] = 0ull; gac2[i][1] = 0ull; }
    mm8x4<128>(Fs, W1 + c0, gac2, n0);

    {
        float4 gb = __ldg(reinterpret_cast<const float4*>(gateb + v * 128 + c0));
        float4 vp = __ldg(reinterpret_cast<const float4*>(view_pref + v * 128 + c0));
#pragma unroll
        for (int i = 0; i < 8; ++i) {
            int n = nb + n0 + i;
            float2 g0 = u2f(gac2[i][0]), g1 = u2f(gac2[i][1]);
            float2 a0 = u2f(acc2[i][0]), a1 = u2f(acc2[i][1]);
            float vo0 = sigm(g0.x + gb.x) * a0.x;
            float vo1 = sigm(g0.y + gb.y) * a0.y;
            float vo2 = sigm(g1.x + gb.z) * a1.x;
            float vo3 = sigm(g1.y + gb.w) * a1.y;
            if (n < NN)
                *reinterpret_cast<float4*>(g_viewout + ((size_t)v * NN + n) * 128 + c0) =
                    make_float4(vo0, vo1, vo2, vo3);
            *reinterpret_cast<float4*>(Fs + (n0 + i) * 128 + c0) =
                make_float4(vo0 * vp.x, vo1 * vp.y, vo2 * vp.z, vo3 * vp.w);
        }
    }
    __syncwarp();

    // ---- view-attention score ----
    ull vac[8];
    MBAR_WAIT(mb0, 1);
#pragma unroll
    for (int i = 0; i < 8; ++i) vac[i] = 0ull;
    mm8x2_64(Fs, W0 + lane * 2, vac, n0);
    {
        int cv = lane * 2;
        float2 vb = __ldg(reinterpret_cast<const float2*>(vattb1 + cv));
        float2 vw = __ldg(reinterpret_cast<const float2*>(vattW2 + cv));
        float b2v = __ldg(vattb2);
#pragma unroll
        for (int i = 0; i < 8; ++i) {
            float2 f0 = u2f(vac[i]);
            float s = fmaxf(f0.x + vb.x, 0.f) * vw.x + fmaxf(f0.y + vb.y, 0.f) * vw.y;
            s = wred32(s);
            int n = nb + n0 + i;
            if (lane == 0 && n < NN) g_vscore[v * NN + n] = s + b2v;
        }
    }
}

// ---------------- fusion + residual + layer norm ----------------
// smem: [0:4) mbars | Zs 16384 | W0 16384 | W1 16384 | vwA 384
__global__ void __launch_bounds__(NT, 1) k_fuse(
    const float* __restrict__ feats,
    const float* __restrict__ fusW,
    const float* __restrict__ ln_g, const float* __restrict__ ln_b,
    float* __restrict__ out) {
    extern __shared__ float sm[];
    float* Zs = sm + 4;
    float* W0 = Zs + 16384;
    float* W1 = W0 + 16384;
    float* vwA = W1 + 16384;
    unsigned mb0 = smaddr(sm), mb1 = mb0 + 8;

    int nb = blockIdx.x * BN;
    int t = threadIdx.x;
    int lane = t & 31;
    int ng = t >> 5;
    int n0 = ng * 8, c0 = lane * 4;

    if (t == 0) { MBAR_INIT(mb0); MBAR_INIT(mb1); }
    __syncthreads();
    if (t == 0) {
        MBAR_EXPECT(mb0, 65536u);
        bulk_g2s(smaddr(W0), g_W01, 65536u, mb0);
        MBAR_EXPECT(mb1, 65536u);
        bulk_g2s(smaddr(W1), fusW + 16384, 65536u, mb1);
    }
    if (t < 128) {
        int n = nb + t;
        float s0 = 0.f, s1 = 0.f, s2 = 0.f, na = 0.f;
        if (n < NN) {
            s0 = g_vscore[n];
            s1 = g_vscore[NN + n];
            s2 = g_vscore[2 * NN + n];
            na = g_nodeatt[n];
        }
        float m = fmaxf(s0, fmaxf(s1, s2));
        float e0 = __expf(s0 - m), e1 = __expf(s1 - m), e2 = __expf(s2 - m);
        float inv = na / (e0 + e1 + e2);
        vwA[t] = e0 * inv;
        vwA[128 + t] = e1 * inv;
        vwA[256 + t] = e2 * inv;
    }
    load_rows_warp(feats, nb, n0, lane, Zs);
    __syncthreads();   // vwA visible

    // phase A: feats @ W01  (== self_out @ fusW[0:128))
    ull acc2[8][2];
    MBAR_WAIT(mb0, 0);
    ZERO_ACC(acc2);
    mm8x4<128>(Zs, W0 + c0, acc2, n0);

    // phase B: rebuild own rows of Zs = weighted view combo (warp-private)
#pragma unroll
    for (int i = 0; i < 8; ++i) {
        int nl = n0 + i;
        int n = nb + nl;
        float4 a = make_float4(0.f, 0.f, 0.f, 0.f);
        if (n < NN) {
            float w0 = vwA[nl], w1 = vwA[128 + nl], w2 = vwA[256 + nl];
            float4 x0 = reinterpret_cast<const float4*>(g_viewout + (size_t)n * 128)[lane];
            float4 x1 = reinterpret_cast<const float4*>(g_viewout + ((size_t)NN + n) * 128)[lane];
            float4 x2 = reinterpret_cast<const float4*>(g_viewout + ((size_t)2 * NN + n) * 128)[lane];
            a.x = w0 * x0.x + w1 * x1.x + w2 * x2.x;
            a.y = w0 * x0.y + w1 * x1.y + w2 * x2.y;
            a.z = w0 * x0.z + w1 * x1.z + w2 * x2.z;
            a.w = w0 * x0.w + w1 * x1.w + w2 * x2.w;
        }
        reinterpret_cast<float4*>(Zs + nl * 128)[lane] = a;
    }
    __syncwarp();
    MBAR_WAIT(mb1, 0);
    mm8x4<128>(Zs, W1 + c0, acc2, n0);

    // epilogue: relu(+b01) + transformed, LN via warp reduce
    {
        float4 fb = __ldg(reinterpret_cast<const float4*>(g_b01 + c0));
        float4 lg = __ldg(reinterpret_cast<const float4*>(ln_g + c0));
        float4 lb = __ldg(reinterpret_cast<const float4*>(ln_b + c0));
#pragma unroll
        for (int i = 0; i < 8; ++i) {
            int n = nb + n0 + i;
            if (n >= NN) continue;   // uniform across warp
            float4 tr = *reinterpret_cast<const float4*>(g_transformed + (size_t)n * 128 + c0);
            float2 l0 = u2f(acc2[i][0]), l1 = u2f(acc2[i][1]);
            float f0 = fmaxf(l0.x + fb.x, 0.f) + tr.x;
            float f1 = fmaxf(l0.y + fb.y, 0.f) + tr.y;
            float f2 = fmaxf(l1.x + fb.z, 0.f) + tr.z;
            float f3 = fmaxf(l1.y + fb.w, 0.f) + tr.w;
            float s = f0 + f1 + f2 + f3;
            float s2 = f0 * f0 + f1 * f1 + f2 * f2 + f3 * f3;
            s = wred32(s);
            s2 = wred32(s2);
            float mu = s * (1.f / 128.f);
            float var = s2 * (1.f / 128.f) - mu * mu;
            float rs = rsqrtf(var + EPSL);
            *reinterpret_cast<float4*>(out + (size_t)n * 128 + c0) =
                make_float4((f0 - mu) * rs * lg.x + lb.x,
                            (f1 - mu) * rs * lg.y + lb.y,
                            (f2 - mu) * rs * lg.z + lb.z,
                            (f3 - mu) * rs * lg.w + lb.w);
        }
    }
}

// ---------------- launch ----------------
extern "C" void kernel_launch(void* const* d_in, const int* in_sizes, int n_in,
                              void* d_out, int out_size) {
    const float* feats   = (const float*)d_in[0];
    const int*   esrc    = (const int*)d_in[1];
    const int*   edst    = (const int*)d_in[2];
    const float* ew      = (const float*)d_in[3];
    const float* clsW    = (const float*)d_in[4];
    const float* clsb    = (const float*)d_in[5];
    const float* attW1   = (const float*)d_in[6];
    const float* attb1   = (const float*)d_in[7];
    const float* attW2   = (const float*)d_in[8];
    const float* attb2   = (const float*)d_in[9];
    const float* attbias = (const float*)d_in[10];
    const float* relW    = (const float*)d_in[11];
    const float* relb    = (const float*)d_in[12];
    const float* gateW   = (const float*)d_in[13];
    const float* gateb   = (const float*)d_in[14];
    const float* vpref   = (const float*)d_in[15];
    const float* vattW1  = (const float*)d_in[16];
    const float* vattb1  = (const float*)d_in[17];
    const float* vattW2  = (const float*)d_in[18];
    const float* vattb2  = (const float*)d_in[19];
    const float* selfW   = (const float*)d_in[20];
    const float* selfb   = (const float*)d_in[21];
    const float* featW   = (const float*)d_in[22];
    const float* featb   = (const float*)d_in[23];
    const float* fusW    = (const float*)d_in[24];
    const float* fusb    = (const float*)d_in[25];
    const float* lng     = (const float*)d_in[26];
    const float* lnb     = (const float*)d_in[27];

    float* out = (float*)d_out;
    float* out_cp = out + (size_t)NN * 128;

    const int SMEM_FEAT = (4 + 16384 * 3 + 256 + 256) * 4;
    const int SMEM_VIEW = (4 + 16384 * 3 + 128) * 4;
    const int SMEM_FUSE = (4 + 16384 * 3 + 384) * 4;

    cudaFuncSetAttribute(k_feat, cudaFuncAttributeMaxDynamicSharedMemorySize, SMEM_FEAT);
    cudaFuncSetAttribute(k_view, cudaFuncAttributeMaxDynamicSharedMemorySize, SMEM_VIEW);
    cudaFuncSetAttribute(k_fuse, cudaFuncAttributeMaxDynamicSharedMemorySize, SMEM_FUSE);

    k_zero<<<2048, 256>>>();
    k_pre<<<128, 128>>>(selfW, selfb, fusW, fusb);

    {
        long long warps = (long long)VV * EE;
        int blocks = (int)((warps * 32 + 255) / 256);
        k_edge<<<blocks, 256>>>(esrc, edst, ew, feats);
    }

    k_feat<<<NTILES, NT, SMEM_FEAT>>>(feats, clsW, clsb, attW1, attb1, attW2, attb2,
                                      attbias, featW, featb, out_cp);

    dim3 gv(NTILES, VV);
    k_view<<<gv, NT, SMEM_VIEW>>>(relW, relb, gateW, gateb, vpref,
                                  vattW1, vattb1, vattW2, vattb2);

    k_fuse<<<NTILES, NT, SMEM_FUSE>>>(feats, fusW, lng, lnb, out);
}

// round 8
// speedup vs baseline: 1.5537x; 1.0195x over previous
#include <cuda_runtime.h>
#include <cstdint>

// ---------------- problem constants ----------------
#define NN 100000
#define VV 3
#define EE 500000
#define EPSL 1e-5f

#define BN 128         // nodes per tile
#define NT 512         // 16 warps; warp = 8-node row group
#define NTILES ((NN + BN - 1) / BN)   // 782

typedef unsigned long long ull;

// ---------------- scratch (device globals; no allocation) ----------------
__device__ float g_pre[(size_t)VV * NN * 128];
__device__ float g_wsum[VV * NN];
__device__ float g_transformed[(size_t)NN * 128];
__device__ float g_nodeatt[NN];
__device__ float g_viewout[(size_t)VV * NN * 128];
__device__ float g_vscore[VV * NN];
__device__ float g_W01[128 * 128];    // selfW @ fusW[0:128]
__device__ float g_b01[128];          // fusb + selfb @ fusW[0:128]

// ---------------- small helpers ----------------
__device__ __forceinline__ void ffma2(ull &d, ull a, ull b) {
    asm("fma.rn.f32x2 %0, %1, %2, %0;" : "+l"(d) : "l"(a), "l"(b));
}
__device__ __forceinline__ ull fdup(float a) {
    ull r; asm("mov.b64 %0, {%1, %1};" : "=l"(r) : "f"(a)); return r;
}
__device__ __forceinline__ float2 u2f(ull v) {
    float2 r; asm("mov.b64 {%0, %1}, %2;" : "=f"(r.x), "=f"(r.y) : "l"(v)); return r;
}
__device__ __forceinline__ float sigm(float x) { return 1.f / (1.f + __expf(-x)); }

__device__ __forceinline__ unsigned smaddr(const void* p) {
    unsigned r;
    asm("{ .reg .u64 t; cvta.to.shared.u64 t, %1; cvt.u32.u64 %0, t; }" : "=r"(r) : "l"(p));
    return r;
}
#define MBAR_INIT(a) asm volatile("mbarrier.init.shared.b64 [%0], 1;" :: "r"(a))
#define MBAR_EXPECT(a, bytes) \
    asm volatile("mbarrier.arrive.expect_tx.shared.b64 _, [%0], %1;" :: "r"(a), "r"(bytes))
#define MBAR_WAIT(a, parity) do { \
    unsigned _p = 0; \
    while (!_p) { \
        asm volatile("{\n\t.reg .pred P;\n\t" \
                     "mbarrier.try_wait.parity.shared.b64 P, [%1], %2, 0x989680;\n\t" \
                     "selp.u32 %0, 1, 0, P;\n\t}" \
                     : "=r"(_p) : "r"(a), "r"((unsigned)(parity))); \
    } } while (0)

__device__ __forceinline__ void bulk_g2s(unsigned dst, const void* src, unsigned bytes, unsigned mbar) {
    asm volatile("cp.async.bulk.shared::cluster.global.mbarrier::complete_tx::bytes [%0], [%1], %2, [%3];"
                 :: "r"(dst), "l"(src), "r"(bytes), "r"(mbar) : "memory");
}

__device__ __forceinline__ float wred32(float x) {
#pragma unroll
    for (int off = 16; off > 0; off >>= 1)
        x += __shfl_xor_sync(0xffffffffu, x, off);
    return x;
}
__device__ __forceinline__ float wred16(float x) {
#pragma unroll
    for (int off = 8; off > 0; off >>= 1)
        x += __shfl_xor_sync(0xffffffffu, x, off);
    return x;
}

// ---------------- zero scratch ----------------
__global__ void k_zero() {
    size_t tid = (size_t)blockIdx.x * blockDim.x + threadIdx.x;
    size_t stride = (size_t)gridDim.x * blockDim.x;
    size_t total4 = ((size_t)VV * NN * 128) / 4;
    float4 z = make_float4(0.f, 0.f, 0.f, 0.f);
    for (size_t i = tid; i < total4; i += stride)
        reinterpret_cast<float4*>(g_pre)[i] = z;
    for (size_t i = tid; i < (size_t)VV * NN; i += stride)
        g_wsum[i] = 0.f;
}

// ---------------- precompute W01 = selfW @ fusW[0:128), b01 = fusb + selfb @ fusW1 ----------------
__global__ void k_pre(const float* __restrict__ selfW, const float* __restrict__ selfb,
                      const float* __restrict__ fusW, const float* __restrict__ fusb) {
    int c = threadIdx.x;
    int i = blockIdx.x;
    float s = 0.f;
#pragma unroll 8
    for (int m = 0; m < 128; ++m)
        s = fmaf(selfW[i * 128 + m], __ldg(fusW + m * 128 + c), s);
    g_W01[i * 128 + c] = s;
    if (i == 0) {
        float b = __ldg(fusb + c);
#pragma unroll 8
        for (int m = 0; m < 128; ++m)
            b = fmaf(__ldg(selfb + m), __ldg(fusW + m * 128 + c), b);
        g_b01[c] = b;
    }
}

// ---------------- edge scatter ----------------
__global__ void __launch_bounds__(256) k_edge(const int* __restrict__ src,
                                              const int* __restrict__ dst,
                                              const float* __restrict__ w,
                                              const float* __restrict__ feats) {
    int gw = (int)(((size_t)blockIdx.x * 256 + threadIdx.x) >> 5);
    if (gw >= VV * EE) return;
    int l = threadIdx.x & 31;
    int v = gw / EE;
    int s = src[gw];
    int d = dst[gw];
    float we = w[gw];
    float4 x = reinterpret_cast<const float4*>(feats + (size_t)s * 128)[l];
    float* p = g_pre + ((size_t)v * NN + d) * 128 + l * 4;
    asm volatile("red.global.add.v4.f32 [%0], {%1,%2,%3,%4};" ::
                 "l"(p), "f"(we * x.x), "f"(we * x.y), "f"(we * x.z), "f"(we * x.w)
                 : "memory");
    if (l == 0) atomicAdd(&g_wsum[v * NN + d], we);
}

// ---------------- warp-private tile loader ----------------
__device__ __forceinline__ void load_rows_warp(const float* __restrict__ g, int nb, int n0,
                                               int lane, float* __restrict__ Fs) {
#pragma unroll
    for (int i = 0; i < 8; ++i) {
        int n = nb + n0 + i;
        float4 v = make_float4(0.f, 0.f, 0.f, 0.f);
        if (n < NN) v = reinterpret_cast<const float4*>(g + (size_t)n * 128)[lane];
        reinterpret_cast<float4*>(Fs + (n0 + i) * 128)[lane] = v;
    }
}

// ---------------- 8x4 register-blocked matmul, FFMA2, broadcast A ----------------
template <int BSTRIDE>
__device__ __forceinline__ void mm8x4(const float* __restrict__ Fs, const float* __restrict__ wbase,
                                      ull acc2[8][2], int n0) {
#pragma unroll 2
    for (int kk = 0; kk < 128; kk += 4) {
        float4 a4[8];
#pragma unroll
        for (int i = 0; i < 8; ++i)
            a4[i] = *reinterpret_cast<const float4*>(Fs + (n0 + i) * 128 + kk);
#pragma unroll
        for (int q = 0; q < 4; ++q) {
            ulonglong2 b = *reinterpret_cast<const ulonglong2*>(wbase + (kk + q) * BSTRIDE);
#pragma unroll
            for (int i = 0; i < 8; ++i) {
                float av = (q == 0) ? a4[i].x : (q == 1) ? a4[i].y : (q == 2) ? a4[i].z : a4[i].w;
                ull ad = fdup(av);
                ffma2(acc2[i][0], ad, b.x);
                ffma2(acc2[i][1], ad, b.y);
            }
        }
    }
}

__device__ __forceinline__ void mm8x2_64(const float* __restrict__ Fs, const float* __restrict__ wbase,
                                         ull acc[8], int n0) {
#pragma unroll 2
    for (int kk = 0; kk < 128; kk += 4) {
        float4 a4[8];
#pragma unroll
        for (int i = 0; i < 8; ++i)
            a4[i] = *reinterpret_cast<const float4*>(Fs + (n0 + i) * 128 + kk);
#pragma unroll
        for (int q = 0; q < 4; ++q) {
            ull b = *reinterpret_cast<const ull*>(wbase + (kk + q) * 64);
#pragma unroll
            for (int i = 0; i < 8; ++i) {
                float av = (q == 0) ? a4[i].x : (q == 1) ? a4[i].y : (q == 2) ? a4[i].z : a4[i].w;
                ffma2(acc[i], fdup(av), b);
            }
        }
    }
}

#define ZERO_ACC(acc2) do { \
    _Pragma("unroll") for (int i = 0; i < 8; ++i) { acc2[i][0] = 0ull; acc2[i][1] = 0ull; } } while (0)

// ---------------- feature-side kernel (warp-synchronous after init) ----------------
// smem: [0:8) mbars | Fs 16384 | W0 16384 | W1 16384
__global__ void __launch_bounds__(NT, 1) k_feat(
    const float* __restrict__ feats,
    const float* __restrict__ clsW, const float* __restrict__ clsb,
    const float* __restrict__ attW1, const float* __restrict__ attb1,
    const float* __restrict__ attW2, const float* __restrict__ attb2,
    const float* __restrict__ attbias,
    const float* __restrict__ featW, const float* __restrict__ featb,
    float* __restrict__ out_cp) {
    extern __shared__ float sm[];
    float* Fs = sm + 8;
    float* W0 = Fs + 16384;
    float* W1 = W0 + 16384;
    unsigned mb0 = smaddr(sm), mb1 = mb0 + 8;

    int nb = blockIdx.x * BN;
    int t = threadIdx.x;
    int lane = t & 31;
    int ng = t >> 5;
    int n0 = ng * 8, c0 = lane * 4;

    if (t == 0) { MBAR_INIT(mb0); MBAR_INIT(mb1); }
    __syncthreads();
    if (t == 0) {
        MBAR_EXPECT(mb0, 65536u);
        bulk_g2s(smaddr(W0), featW, 65536u, mb0);
        MBAR_EXPECT(mb1, 65536u);
        bulk_g2s(smaddr(W1), attW1, 65536u, mb1);
    }
    load_rows_warp(feats, nb, n0, lane, Fs);
    __syncwarp();

    ull acc2[8][2];

    // ---- transformed = f @ featW + featb ----
    MBAR_WAIT(mb0, 0);
    ZERO_ACC(acc2);
    mm8x4<128>(Fs, W0 + c0, acc2, n0);
    {
        float4 b0 = __ldg(reinterpret_cast<const float4*>(featb + c0));
#pragma unroll
        for (int i = 0; i < 8; ++i) {
            int n = nb + n0 + i;
            if (n < NN) {
                float2 p0 = u2f(acc2[i][0]), p1 = u2f(acc2[i][1]);
                *reinterpret_cast<float4*>(g_transformed + (size_t)n * 128 + c0) =
                    make_float4(p0.x + b0.x, p0.y + b0.y, p1.x + b0.z, p1.y + b0.w);
            }
        }
    }

    // ---- label attention: sc (own class half), sco (other class) in registers ----
    float sc[8], sco[8];
    MBAR_WAIT(mb1, 0);
    ZERO_ACC(acc2);
    {
        int cls = c0 >> 6;
        mm8x4<64>(Fs, W1 + cls * 8192 + (c0 & 63), acc2, n0);
        float4 ab = __ldg(reinterpret_cast<const float4*>(attb1 + c0));
        float4 aw = __ldg(reinterpret_cast<const float4*>(attW2 + c0));
        float b2v = __ldg(attb2 + cls);
#pragma unroll
        for (int i = 0; i < 8; ++i) {
            float2 f0 = u2f(acc2[i][0]), f1 = u2f(acc2[i][1]);
            float p = fmaxf(f0.x + ab.x, 0.f) * aw.x
                    + fmaxf(f0.y + ab.y, 0.f) * aw.y
                    + fmaxf(f1.x + ab.z, 0.f) * aw.z
                    + fmaxf(f1.y + ab.w, 0.f) * aw.w;
            p = wred16(p);
            sc[i] = sigm(p + b2v);
            sco[i] = __shfl_xor_sync(0xffffffffu, sc[i], 16);
        }
    }

    // ---- class probs + node_att (warp-private: lane partials over own 4 dims) ----
    {
        // clsW is [128][2]; lane's 4 input dims are c0..c0+3
        float4 cw0 = __ldg(reinterpret_cast<const float4*>(clsW + c0 * 2));
        float4 cw1 = __ldg(reinterpret_cast<const float4*>(clsW + c0 * 2) + 1);
        float cb0 = __ldg(clsb), cb1 = __ldg(clsb + 1), abv = __ldg(attbias);
#pragma unroll
        for (int i = 0; i < 8; ++i) {
            float4 f = *reinterpret_cast<const float4*>(Fs + (n0 + i) * 128 + c0);
            float p0 = f.x * cw0.x + f.y * cw0.z + f.z * cw1.x + f.w * cw1.z;
            float p1 = f.x * cw0.y + f.y * cw0.w + f.z * cw1.y + f.w * cw1.w;
            p0 = wred32(p0);
            p1 = wred32(p1);
            int n = nb + n0 + i;
            if (lane == 0 && n < NN) {
                float l0 = p0 + cb0, l1 = p1 + cb1;
                float m = fmaxf(l0, l1);
                float e0 = __expf(l0 - m), e1 = __expf(l1 - m);
                float inv = 1.f / (e0 + e1);
                float cp0 = e0 * inv, cp1 = e1 * inv;
                out_cp[(size_t)n * 2] = cp0;
                out_cp[(size_t)n * 2 + 1] = cp1;
                g_nodeatt[n] = sc[i] * cp0 + sco[i] * cp1 + abv;   // lane0 is class-0 half
            }
        }
    }
}

// ---------------- per-view kernel (warp-synchronous after init) ----------------
// smem: [0:8) mbars | Fs 16384 | W0 16384 | W1 16384 | W2 8192
__global__ void __launch_bounds__(NT, 1) k_view(
    const float* __restrict__ relW, const float* __restrict__ relb,
    const float* __restrict__ gateW, const float* __restrict__ gateb,
    const float* __restrict__ view_pref,
    const float* __restrict__ vattW1, const float* __restrict__ vattb1,
    const float* __restrict__ vattW2, const float* __restrict__ vattb2) {
    extern __shared__ float sm[];
    float* Fs = sm + 8;
    float* W0 = Fs + 16384;
    float* W1 = W0 + 16384;
    float* W2 = W1 + 16384;
    unsigned mb0 = smaddr(sm), mb1 = mb0 + 8, mb2 = mb0 + 16;

    int v = blockIdx.y;
    int nb = blockIdx.x * BN;
    int t = threadIdx.x;
    int lane = t & 31;
    int ng = t >> 5;
    int n0 = ng * 8, c0 = lane * 4;

    if (t == 0) { MBAR_INIT(mb0); MBAR_INIT(mb1); MBAR_INIT(mb2); }
    __syncthreads();
    if (t == 0) {
        MBAR_EXPECT(mb0, 65536u);
        bulk_g2s(smaddr(W0), relW + (size_t)v * 16384, 65536u, mb0);
        MBAR_EXPECT(mb1, 65536u);
        bulk_g2s(smaddr(W1), gateW + (size_t)v * 16384, 65536u, mb1);
        MBAR_EXPECT(mb2, 32768u);
        bulk_g2s(smaddr(W2), vattW1, 32768u, mb2);
    }
    load_rows_warp(g_pre + (size_t)v * NN * 128, nb, n0, lane, Fs);
    // wsum for own 8 nodes on lanes 0..7
    float ws_r = 0.f;
    if (lane < 8) {
        int n = nb + n0 + lane;
        if (n < NN) ws_r = __ldg(g_wsum + v * NN + n);
    }
    __syncwarp();

    // ---- agg = pre @ relW + wsum * relb ----
    ull acc2[8][2];
    MBAR_WAIT(mb0, 0);
    ZERO_ACC(acc2);
    mm8x4<128>(Fs, W0 + c0, acc2, n0);
    {
        ulonglong2 r01 = __ldg(reinterpret_cast<const ulonglong2*>(relb + v * 128 + c0));
#pragma unroll
        for (int i = 0; i < 8; ++i) {
            ull wd = fdup(__shfl_sync(0xffffffffu, ws_r, i));
            ffma2(acc2[i][0], wd, r01.x);
            ffma2(acc2[i][1], wd, r01.y);
        }
    }
    // stash agg into own rows (warp-private)
#pragma unroll
    for (int i = 0; i < 8; ++i) {
        float2 p0 = u2f(acc2[i][0]), p1 = u2f(acc2[i][1]);
        *reinterpret_cast<float4*>(Fs + (n0 + i) * 128 + c0) = make_float4(p0.x, p0.y, p1.x, p1.y);
    }
    __syncwarp();

    // ---- gate matmul on agg ----
    ull gac2[8][2];
    MBAR_WAIT(mb1, 0);
#pragma unroll
    for (int i = 0; i < 8; ++i) { gac2[i][0] = 0ull; gac2[i][1] = 0ull; }
    mm8x4<128>(Fs, W1 + c0, gac2, n0);

    {
        float4 gb = __ldg(reinterpret_cast<const float4*>(gateb + v * 128 + c0));
        float4 vp = __ldg(reinterpret_cast<const float4*>(view_pref + v * 128 + c0));
#pragma unroll
        for (int i = 0; i < 8; ++i) {
            int n = nb + n0 + i;
            float2 g0 = u2f(gac2[i][0]), g1 = u2f(gac2[i][1]);
            float2 a0 = u2f(acc2[i][0]), a1 = u2f(acc2[i][1]);
            float vo0 = sigm(g0.x + gb.x) * a0.x;
            float vo1 = sigm(g0.y + gb.y) * a0.y;
            float vo2 = sigm(g1.x + gb.z) * a1.x;
            float vo3 = sigm(g1.y + gb.w) * a1.y;
            if (n < NN)
                *reinterpret_cast<float4*>(g_viewout + ((size_t)v * NN + n) * 128 + c0) =
                    make_float4(vo0, vo1, vo2, vo3);
            *reinterpret_cast<float4*>(Fs + (n0 + i) * 128 + c0) =
                make_float4(vo0 * vp.x, vo1 * vp.y, vo2 * vp.z, vo3 * vp.w);
        }
    }
    __syncwarp();

    // ---- view-attention score ----
    ull vac[8];
    MBAR_WAIT(mb2, 0);
#pragma unroll
    for (int i = 0; i < 8; ++i) vac[i] = 0ull;
    mm8x2_64(Fs, W2 + lane * 2, vac, n0);
    {
        int cv = lane * 2;
        float2 vb = __ldg(reinterpret_cast<const float2*>(vattb1 + cv));
        float2 vw = __ldg(reinterpret_cast<const float2*>(vattW2 + cv));
        float b2v = __ldg(vattb2);
#pragma unroll
        for (int i = 0; i < 8; ++i) {
            float2 f0 = u2f(vac[i]);
            float s = fmaxf(f0.x + vb.x, 0.f) * vw.x + fmaxf(f0.y + vb.y, 0.f) * vw.y;
            s = wred32(s);
            int n = nb + n0 + i;
            if (lane == 0 && n < NN) g_vscore[v * NN + n] = s + b2v;
        }
    }
}

// ---------------- fusion + residual + layer norm (warp-synchronous after init) ----------------
// smem: [0:8) mbars | Zs 16384 | W0 16384 | W1 16384
__global__ void __launch_bounds__(NT, 1) k_fuse(
    const float* __restrict__ feats,
    const float* __restrict__ fusW,
    const float* __restrict__ ln_g, const float* __restrict__ ln_b,
    float* __restrict__ out) {
    extern __shared__ float sm[];
    float* Zs = sm + 8;
    float* W0 = Zs + 16384;
    float* W1 = W0 + 16384;
    unsigned mb0 = smaddr(sm), mb1 = mb0 + 8;

    int nb = blockIdx.x * BN;
    int t = threadIdx.x;
    int lane = t & 31;
    int ng = t >> 5;
    int n0 = ng * 8, c0 = lane * 4;

    if (t == 0) { MBAR_INIT(mb0); MBAR_INIT(mb1); }
    __syncthreads();
    if (t == 0) {
        MBAR_EXPECT(mb0, 65536u);
        bulk_g2s(smaddr(W0), g_W01, 65536u, mb0);
        MBAR_EXPECT(mb1, 65536u);
        bulk_g2s(smaddr(W1), fusW + 16384, 65536u, mb1);
    }
    // per-node softmax-over-views * node_att on lanes 0..7
    float vw0_r = 0.f, vw1_r = 0.f, vw2_r = 0.f;
    if (lane < 8) {
        int n = nb + n0 + lane;
        float s0 = 0.f, s1 = 0.f, s2 = 0.f, na = 0.f;
        if (n < NN) {
            s0 = __ldg(g_vscore + n);
            s1 = __ldg(g_vscore + NN + n);
            s2 = __ldg(g_vscore + 2 * NN + n);
            na = __ldg(g_nodeatt + n);
        }
        float m = fmaxf(s0, fmaxf(s1, s2));
        float e0 = __expf(s0 - m), e1 = __expf(s1 - m), e2 = __expf(s2 - m);
        float inv = na / (e0 + e1 + e2);
        vw0_r = e0 * inv; vw1_r = e1 * inv; vw2_r = e2 * inv;
    }
    load_rows_warp(feats, nb, n0, lane, Zs);
    __syncwarp();

    // phase A: feats @ W01  (== self_out @ fusW[0:128))
    ull acc2[8][2];
    MBAR_WAIT(mb0, 0);
    ZERO_ACC(acc2);
    mm8x4<128>(Zs, W0 + c0, acc2, n0);

    // phase B: rebuild own rows = weighted view combo (warp-private)
#pragma unroll
    for (int i = 0; i < 8; ++i) {
        int nl = n0 + i;
        int n = nb + nl;
        float w0 = __shfl_sync(0xffffffffu, vw0_r, i);
        float w1 = __shfl_sync(0xffffffffu, vw1_r, i);
        float w2 = __shfl_sync(0xffffffffu, vw2_r, i);
        float4 a = make_float4(0.f, 0.f, 0.f, 0.f);
        if (n < NN) {
            float4 x0 = reinterpret_cast<const float4*>(g_viewout + (size_t)n * 128)[lane];
            float4 x1 = reinterpret_cast<const float4*>(g_viewout + ((size_t)NN + n) * 128)[lane];
            float4 x2 = reinterpret_cast<const float4*>(g_viewout + ((size_t)2 * NN + n) * 128)[lane];
            a.x = w0 * x0.x + w1 * x1.x + w2 * x2.x;
            a.y = w0 * x0.y + w1 * x1.y + w2 * x2.y;
            a.z = w0 * x0.z + w1 * x1.z + w2 * x2.z;
            a.w = w0 * x0.w + w1 * x1.w + w2 * x2.w;
        }
        reinterpret_cast<float4*>(Zs + nl * 128)[lane] = a;
    }
    __syncwarp();
    MBAR_WAIT(mb1, 0);
    mm8x4<128>(Zs, W1 + c0, acc2, n0);

    // epilogue: relu(+b01) + transformed, LN via warp reduce
    {
        float4 fb = __ldg(reinterpret_cast<const float4*>(g_b01 + c0));
        float4 lg = __ldg(reinterpret_cast<const float4*>(ln_g + c0));
        float4 lb = __ldg(reinterpret_cast<const float4*>(ln_b + c0));
#pragma unroll
        for (int i = 0; i < 8; ++i) {
            int n = nb + n0 + i;
            if (n >= NN) continue;   // uniform across warp
            float4 tr = *reinterpret_cast<const float4*>(g_transformed + (size_t)n * 128 + c0);
            float2 l0 = u2f(acc2[i][0]), l1 = u2f(acc2[i][1]);
            float f0 = fmaxf(l0.x + fb.x, 0.f) + tr.x;
            float f1 = fmaxf(l0.y + fb.y, 0.f) + tr.y;
            float f2 = fmaxf(l1.x + fb.z, 0.f) + tr.z;
            float f3 = fmaxf(l1.y + fb.w, 0.f) + tr.w;
            float s = f0 + f1 + f2 + f3;
            float s2 = f0 * f0 + f1 * f1 + f2 * f2 + f3 * f3;
            s = wred32(s);
            s2 = wred32(s2);
            float mu = s * (1.f / 128.f);
            float var = s2 * (1.f / 128.f) - mu * mu;
            float rs = rsqrtf(var + EPSL);
            *reinterpret_cast<float4*>(out + (size_t)n * 128 + c0) =
                make_float4((f0 - mu) * rs * lg.x + lb.x,
                            (f1 - mu) * rs * lg.y + lb.y,
                            (f2 - mu) * rs * lg.z + lb.z,
                            (f3 - mu) * rs * lg.w + lb.w);
        }
    }
}

// ---------------- launch ----------------
extern "C" void kernel_launch(void* const* d_in, const int* in_sizes, int n_in,
                              void* d_out, int out_size) {
    const float* feats   = (const float*)d_in[0];
    const int*   esrc    = (const int*)d_in[1];
    const int*   edst    = (const int*)d_in[2];
    const float* ew      = (const float*)d_in[3];
    const float* clsW    = (const float*)d_in[4];
    const float* clsb    = (const float*)d_in[5];
    const float* attW1   = (const float*)d_in[6];
    const float* attb1   = (const float*)d_in[7];
    const float* attW2   = (const float*)d_in[8];
    const float* attb2   = (const float*)d_in[9];
    const float* attbias = (const float*)d_in[10];
    const float* relW    = (const float*)d_in[11];
    const float* relb    = (const float*)d_in[12];
    const float* gateW   = (const float*)d_in[13];
    const float* gateb   = (const float*)d_in[14];
    const float* vpref   = (const float*)d_in[15];
    const float* vattW1  = (const float*)d_in[16];
    const float* vattb1  = (const float*)d_in[17];
    const float* vattW2  = (const float*)d_in[18];
    const float* vattb2  = (const float*)d_in[19];
    const float* selfW   = (const float*)d_in[20];
    const float* selfb   = (const float*)d_in[21];
    const float* featW   = (const float*)d_in[22];
    const float* featb   = (const float*)d_in[23];
    const float* fusW    = (const float*)d_in[24];
    const float* fusb    = (const float*)d_in[25];
    const float* lng     = (const float*)d_in[26];
    const float* lnb     = (const float*)d_in[27];

    float* out = (float*)d_out;
    float* out_cp = out + (size_t)NN * 128;

    const int SMEM_FEAT = (8 + 16384 * 3) * 4;
    const int SMEM_VIEW = (8 + 16384 * 3 + 8192) * 4;
    const int SMEM_FUSE = (8 + 16384 * 3) * 4;

    cudaFuncSetAttribute(k_feat, cudaFuncAttributeMaxDynamicSharedMemorySize, SMEM_FEAT);
    cudaFuncSetAttribute(k_view, cudaFuncAttributeMaxDynamicSharedMemorySize, SMEM_VIEW);
    cudaFuncSetAttribute(k_fuse, cudaFuncAttributeMaxDynamicSharedMemorySize, SMEM_FUSE);

    k_zero<<<2048, 256>>>();
    k_pre<<<128, 128>>>(selfW, selfb, fusW, fusb);

    {
        long long warps = (long long)VV * EE;
        int blocks = (int)((warps * 32 + 255) / 256);
        k_edge<<<blocks, 256>>>(esrc, edst, ew, feats);
    }

    k_feat<<<NTILES, NT, SMEM_FEAT>>>(feats, clsW, clsb, attW1, attb1, attW2, attb2,
                                      attbias, featW, featb, out_cp);

    dim3 gv(NTILES, VV);
    k_view<<<gv, NT, SMEM_VIEW>>>(relW, relb, gateW, gateb, vpref,
                                  vattW1, vattb1, vattW2, vattb2);

    k_fuse<<<NTILES, NT, SMEM_FUSE>>>(feats, fusW, lng, lnb, out);
}